// round 12
// baseline (speedup 1.0000x reference)
#include <cuda_runtime.h>
#include <math.h>

#define NROWS 16384
#define ZDIM  100
#define EDIM  400
#define MOD0  4000
#define MOD1  2000

// Scratch for topic matrices (beta @ alpha^T), stored row-major (Z, M).
__device__ __align__(16) float g_topic0[ZDIM * MOD0];
__device__ __align__(16) float g_topic1[ZDIM * MOD1];

typedef unsigned long long ull;

__device__ __forceinline__ ull fma2(ull a, ull b, ull c) {
    ull d;
    asm("fma.rn.f32x2 %0, %1, %2, %3;" : "=l"(d) : "l"(a), "l"(b), "l"(c));
    return d;
}
__device__ __forceinline__ ull dup2(float x) {
    ull d;
    unsigned u = __float_as_uint(x);
    asm("mov.b64 %0, {%1, %1};" : "=l"(d) : "r"(u));
    return d;
}
__device__ __forceinline__ float f2lo(ull v) {
    return __uint_as_float((unsigned)v);
}
__device__ __forceinline__ float f2hi(ull v) {
    return __uint_as_float((unsigned)(v >> 32));
}

// ---------------------------------------------------------------------------
// Topic kernel (merged modules): topic = beta @ alpha^T  (Z=100 x M).
// Grid = 192: blocks 0..127 -> M0 (32 col-chunks x 4 z-chunks),
//             blocks 128..191 -> M1 (16 x 4). Each CTA: 25 z x 128 cols.
// ---------------------------------------------------------------------------
__global__ void __launch_bounds__(256)
topic_kernel(const float* __restrict__ alpha0,
             const float* __restrict__ alpha1,
             const float* __restrict__ beta) {
    constexpr int EC = 50;
    __shared__ float a_s[128][EC + 1];
    __shared__ float b_s[32][EC + 1];

    const int bx = blockIdx.x;
    const int mod = (bx >= 128);
    const int local = mod ? bx - 128 : bx;
    const int M = mod ? MOD1 : MOD0;
    const float* __restrict__ alpha = mod ? alpha1 : alpha0;
    float* topic = mod ? g_topic1 : g_topic0;
    const int mbase = (local >> 2) * 128;
    const int zbase = (local & 3) * 25;

    const int tid = threadIdx.x;
    const int tcol = tid & 31;
    const int trow = tid >> 5;

    float acc[4][4];
#pragma unroll
    for (int j = 0; j < 4; j++)
#pragma unroll
        for (int k = 0; k < 4; k++) acc[j][k] = 0.f;

    for (int eb = 0; eb < EDIM; eb += EC) {
        for (int i = tid; i < 128 * EC; i += 256) {
            int mm = i / EC, e = i % EC;
            int gm = mbase + mm;
            a_s[mm][e] = (gm < M) ? alpha[(size_t)gm * EDIM + eb + e] : 0.f;
        }
        for (int i = tid; i < 32 * EC; i += 256) {
            int zz = i / EC, e = i % EC;
            b_s[zz][e] = (zz < 25) ? beta[(size_t)(zbase + zz) * EDIM + eb + e]
                                   : 0.f;
        }
        __syncthreads();
#pragma unroll 2
        for (int e = 0; e < EC; e++) {
            float av[4], bv[4];
#pragma unroll
            for (int k = 0; k < 4; k++) av[k] = a_s[tcol + 32 * k][e];
#pragma unroll
            for (int j = 0; j < 4; j++) bv[j] = b_s[trow + 8 * j][e];
#pragma unroll
            for (int j = 0; j < 4; j++)
#pragma unroll
                for (int k = 0; k < 4; k++) acc[j][k] += bv[j] * av[k];
        }
        __syncthreads();
    }

#pragma unroll
    for (int j = 0; j < 4; j++) {
        int zz = trow + 8 * j;
        if (zz < 25) {
            int z = zbase + zz;
#pragma unroll
            for (int k = 0; k < 4; k++) {
                int m = mbase + tcol + 32 * k;
                if (m < M) topic[(size_t)z * M + m] = acc[j][k];
            }
        }
    }
}

// ---------------------------------------------------------------------------
// Main kernel (merged modules): logits = theta @ topic + bias[dom];
// out = logits - logsumexp. CTA: 64 rows. Warp: 8 rows (4 f32x2 row-pairs),
// lane: 4 cols per 128-col tile. Theta SMEM transposed [z][64rows] so one
// broadcast LDS.128 feeds 4 rows (2 packed pairs); topic dup'd via ALU MOV.
// Per-lane online (max,sumexp); one warp butterfly at the end.
// ---------------------------------------------------------------------------
__global__ void __launch_bounds__(256)
main_kernel(const float* __restrict__ theta,
            const float* __restrict__ bias0,
            const float* __restrict__ bias1,
            const int* __restrict__ dom,
            float* __restrict__ out0,
            float* __restrict__ out1) {
    constexpr int R = 64;
    __shared__ __align__(16) float th_s[R * ZDIM];  // [z][row]
    __shared__ int d_s[R];

    const int bx = blockIdx.x;
    const int mod = (bx >= NROWS / R);
    const int bid = mod ? bx - NROWS / R : bx;
    const int M = mod ? MOD1 : MOD0;
    const float* __restrict__ topic = mod ? g_topic1 : g_topic0;
    const float* __restrict__ bias = mod ? bias1 : bias0;
    float* __restrict__ out = mod ? out1 : out0;

    const int tid = threadIdx.x;
    const int tcol = tid & 31;
    const int trow = tid >> 5;
    const int rowbase = bid * R;
    const int r0 = trow * 8;

    // Transposed theta load (uncoalesced global read, one-time 25.6KB/CTA).
    for (int i = tid; i < R * ZDIM; i += 256) {
        int z = i >> 6, row = i & 63;
        th_s[z * R + row] = theta[(size_t)(rowbase + row) * ZDIM + z];
    }
    if (tid < R) d_s[tid] = dom[rowbase + tid];
    __syncthreads();

    float rm[8], rs[8];
#pragma unroll
    for (int i = 0; i < 8; i++) { rm[i] = -1e30f; rs[i] = 0.f; }

    const int NT = (M + 127) >> 7;
    for (int tile = 0; tile < NT; tile++) {
        const int c = tile * 128 + tcol * 4;
        const bool valid = (c < M);
        const float* tc = topic + (valid ? c : 0);

        ull acc[4][4];  // [col][rowpair]
#pragma unroll
        for (int cc = 0; cc < 4; cc++)
#pragma unroll
            for (int p = 0; p < 4; p++) acc[cc][p] = 0ull;

#pragma unroll 5
        for (int z = 0; z < ZDIM; z++) {
            float4 tv = *reinterpret_cast<const float4*>(tc + (size_t)z * M);
            ull t0 = dup2(tv.x), t1 = dup2(tv.y);
            ull t2 = dup2(tv.z), t3 = dup2(tv.w);
            ulonglong2 pA =
                *reinterpret_cast<const ulonglong2*>(&th_s[z * R + r0]);
            ulonglong2 pB =
                *reinterpret_cast<const ulonglong2*>(&th_s[z * R + r0 + 4]);
            acc[0][0] = fma2(pA.x, t0, acc[0][0]);
            acc[0][1] = fma2(pA.y, t0, acc[0][1]);
            acc[0][2] = fma2(pB.x, t0, acc[0][2]);
            acc[0][3] = fma2(pB.y, t0, acc[0][3]);
            acc[1][0] = fma2(pA.x, t1, acc[1][0]);
            acc[1][1] = fma2(pA.y, t1, acc[1][1]);
            acc[1][2] = fma2(pB.x, t1, acc[1][2]);
            acc[1][3] = fma2(pB.y, t1, acc[1][3]);
            acc[2][0] = fma2(pA.x, t2, acc[2][0]);
            acc[2][1] = fma2(pA.y, t2, acc[2][1]);
            acc[2][2] = fma2(pB.x, t2, acc[2][2]);
            acc[2][3] = fma2(pB.y, t2, acc[2][3]);
            acc[3][0] = fma2(pA.x, t3, acc[3][0]);
            acc[3][1] = fma2(pA.y, t3, acc[3][1]);
            acc[3][2] = fma2(pB.x, t3, acc[3][2]);
            acc[3][3] = fma2(pB.y, t3, acc[3][3]);
        }

        if (valid) {
#pragma unroll
            for (int p = 0; p < 4; p++) {
#pragma unroll
                for (int b = 0; b < 2; b++) {
                    const int i8 = 2 * p + b;
                    float l0 = b ? f2hi(acc[0][p]) : f2lo(acc[0][p]);
                    float l1 = b ? f2hi(acc[1][p]) : f2lo(acc[1][p]);
                    float l2 = b ? f2hi(acc[2][p]) : f2lo(acc[2][p]);
                    float l3 = b ? f2hi(acc[3][p]) : f2lo(acc[3][p]);
                    int d = d_s[r0 + i8];
                    float4 bv = *reinterpret_cast<const float4*>(
                        bias + (size_t)d * M + c);
                    l0 += bv.x; l1 += bv.y; l2 += bv.z; l3 += bv.w;
                    *reinterpret_cast<float4*>(
                        out + (size_t)(rowbase + r0 + i8) * M + c) =
                        make_float4(l0, l1, l2, l3);
                    float lm = fmaxf(fmaxf(l0, l1), fmaxf(l2, l3));
                    float nm = fmaxf(rm[i8], lm);
                    rs[i8] = rs[i8] * __expf(rm[i8] - nm) +
                             __expf(l0 - nm) + __expf(l1 - nm) +
                             __expf(l2 - nm) + __expf(l3 - nm);
                    rm[i8] = nm;
                }
            }
        }
    }

    // One warp butterfly per row: merge per-lane (m, s).
    float lse[8];
#pragma unroll
    for (int i = 0; i < 8; i++) {
        float m = rm[i], s = rs[i];
#pragma unroll
        for (int off = 16; off; off >>= 1) {
            float om = __shfl_xor_sync(0xffffffffu, m, off);
            float os = __shfl_xor_sync(0xffffffffu, s, off);
            float nm = fmaxf(m, om);
            s = s * __expf(m - nm) + os * __expf(om - nm);
            m = nm;
        }
        lse[i] = m + logf(s);
    }

    // Phase 2: subtract lse (re-read just-written logits; L2-hot).
    for (int tile = 0; tile < NT; tile++) {
        const int c = tile * 128 + tcol * 4;
        if (c < M) {
#pragma unroll
            for (int i = 0; i < 8; i++) {
                float4* p = reinterpret_cast<float4*>(
                    out + (size_t)(rowbase + r0 + i) * M + c);
                float4 v = *p;
                v.x -= lse[i]; v.y -= lse[i];
                v.z -= lse[i]; v.w -= lse[i];
                *p = v;
            }
        }
    }
}

extern "C" void kernel_launch(void* const* d_in, const int* in_sizes, int n_in,
                              void* d_out, int out_size) {
    const float* theta  = (const float*)d_in[0];
    const float* alpha0 = (const float*)d_in[1];
    const float* alpha1 = (const float*)d_in[2];
    const float* beta   = (const float*)d_in[3];
    const float* bias0  = (const float*)d_in[4];
    const float* bias1  = (const float*)d_in[5];
    const int*   dom    = (const int*)d_in[6];

    float* out0 = (float*)d_out;
    float* out1 = out0 + (size_t)NROWS * MOD0;

    topic_kernel<<<192, 256>>>(alpha0, alpha1, beta);
    main_kernel<<<2 * (NROWS / 64), 256>>>(theta, bias0, bias1, dom, out0,
                                           out1);
}